// round 14
// baseline (speedup 1.0000x reference)
#include <cuda_runtime.h>
#include <cuda_fp16.h>
#include <cstdint>

// CoarseMatching: N=2, L=S=4800, C=256
#define NB 2
#define LL 4800
#define SS 4800
#define CC 256
#define TILE 128
#define NT ((LL + TILE - 1) / TILE)   // 38
#define LPAD (NT * TILE)              // 4864 padded rows
#define BK 64
#define NK (CC / BK)                  // 4
#define PAD 72                        // smem row stride in halves (144B) for BK=64
#define STG_HALVES (TILE * PAD)       // 9216 halves = 18432 B per stage per array
#define STG_BYTES (STG_HALVES * 2)
#define NSTG 3
#define EPAD 136                      // epilogue smem tile row stride in halves (272B)
#define SM_STAGES (2 * NSTG * STG_BYTES)   // 110592 — epilogue tile + csPart overlay inside
#define EX2SC 0.05635527504843507f    // (1/(256*0.1)) * log2(e)
#define THRV 0.2f

// ---------------- device scratch ----------------
__device__ __half g_h0[NB * LPAD * CC];
__device__ __half g_h1[NB * LPAD * CC];
__device__ __half g_E [(size_t)NB * LL * SS];  // e = exp(sim), fp16 (92 MB)
__device__ float  g_R [NB * LL];   // row sums of exp(sim)
__device__ float  g_Cs[NB * SS];   // col sums of exp(sim)
__device__ float  g_iC[NB * SS];   // 1/colsum
__device__ float  g_RM[NB * LL];   // per-row max of conf

// ---------------- PTX helpers ----------------
__device__ __forceinline__ uint32_t sm2u(const void* p) {
    uint32_t a;
    asm("{ .reg .u64 t; cvta.to.shared.u64 t, %1; cvt.u32.u64 %0, t; }" : "=r"(a) : "l"(p));
    return a;
}

__device__ __forceinline__ void ldsm4(uint32_t* r, uint32_t addr) {
    asm volatile("ldmatrix.sync.aligned.m8n8.x4.shared.b16 {%0,%1,%2,%3}, [%4];"
                 : "=r"(r[0]), "=r"(r[1]), "=r"(r[2]), "=r"(r[3]) : "r"(addr));
}

__device__ __forceinline__ void mma16816(float* d, const uint32_t* a, uint32_t b0, uint32_t b1) {
    asm volatile(
        "mma.sync.aligned.m16n8k16.row.col.f32.f16.f16.f32 "
        "{%0,%1,%2,%3}, {%4,%5,%6,%7}, {%8,%9}, {%0,%1,%2,%3};"
        : "+f"(d[0]), "+f"(d[1]), "+f"(d[2]), "+f"(d[3])
        : "r"(a[0]), "r"(a[1]), "r"(a[2]), "r"(a[3]), "r"(b0), "r"(b1));
}

__device__ __forceinline__ void cpa16(uint32_t smem, const void* gmem) {
    asm volatile("cp.async.cg.shared.global [%0], [%1], 16;" :: "r"(smem), "l"(gmem));
}
__device__ __forceinline__ void cpa_commit() {
    asm volatile("cp.async.commit_group;" ::: "memory");
}
#define CPA_WAIT(n) asm volatile("cp.async.wait_group %0;" :: "n"(n) : "memory")

// ---------------- prep (one batch): fp32 -> fp16 with zero padding; nb==0 also zeros ----------------
__global__ void prep_kernel(const float* __restrict__ f0, const float* __restrict__ f1,
                            float* __restrict__ out, long long out_size, int nb) {
    long long i = (long long)blockIdx.x * blockDim.x + threadIdx.x;   // one uint2 (4 halves)
    if (nb == 0) {
        if (i < NB * LL) { g_R[i] = 0.f; g_RM[i] = 0.f; }
        if (i < NB * SS) g_Cs[i] = 0.f;
        long long NLS = (long long)NB * LL * SS;
        long long extras = (long long)3 * NB * LL + NB;
        if (out_size >= NLS + extras && i < extras) out[NLS + i] = 0.f;
    }
    long long n4 = (long long)LPAD * CC / 4;       // per batch
    if (i >= n4) return;
    long long t = i * 4;
    int row = (int)(t / CC), c = (int)(t % CC);
    uint2 z0 = make_uint2(0u, 0u), z1 = make_uint2(0u, 0u);
    if (row < LL) {
        long long s = ((long long)nb * LL + row) * CC + c;
        float4 a = *reinterpret_cast<const float4*>(f0 + s);
        float4 b = *reinterpret_cast<const float4*>(f1 + s);
        __half2 a01 = __floats2half2_rn(a.x, a.y), a23 = __floats2half2_rn(a.z, a.w);
        __half2 b01 = __floats2half2_rn(b.x, b.y), b23 = __floats2half2_rn(b.z, b.w);
        z0 = make_uint2(*(uint32_t*)&a01, *(uint32_t*)&a23);
        z1 = make_uint2(*(uint32_t*)&b01, *(uint32_t*)&b23);
    }
    long long base = (long long)nb * LPAD * CC / 4;
    reinterpret_cast<uint2*>(g_h0)[base + i] = z0;
    reinterpret_cast<uint2*>(g_h1)[base + i] = z1;
}

__global__ void recip_kernel(int nb) {
    int i = blockIdx.x * blockDim.x + threadIdx.x;
    if (i < SS) g_iC[nb * SS + i] = __frcp_rn(g_Cs[nb * SS + i]);
}

// ---------------- GEMM (one batch): e = exp(sim) -> g_E (fp16); row/col sums of e ----------------
__global__ void __launch_bounds__(256, 2) gemm_kernel(int nb) {
    extern __shared__ __align__(16) char smbuf[];
    __half* sA = reinterpret_cast<__half*>(smbuf);
    __half* sB = reinterpret_cast<__half*>(smbuf + NSTG * STG_BYTES);

    const int tid = threadIdx.x, lane = tid & 31, w = tid >> 5;
    const int tn = blockIdx.x, tm = blockIdx.y;

    const __half* A = g_h0 + (size_t)nb * LPAD * CC + (size_t)tm * TILE * CC;
    const __half* B = g_h1 + (size_t)nb * LPAD * CC + (size_t)tn * TILE * CC;

    const uint32_t sAu = sm2u(sA), sBu = sm2u(sB);

    // per chunk: 128 rows x 64 halves (128B) per array -> 1024 16B-vectors, 4/thread/array
    auto stage_load = [&](int kc) {
        int st = kc % NSTG;
#pragma unroll
        for (int h = 0; h < 4; ++h) {
            int v = tid + h * 256;            // 0..1023
            int row = v >> 3, kv = v & 7;     // row 0..127, 16B chunk 0..7
            uint32_t soff = (uint32_t)st * STG_BYTES + (uint32_t)((row * PAD + kv * 8) * 2);
            const __half* ga = A + (size_t)row * CC + kc * BK + kv * 8;
            const __half* gb = B + (size_t)row * CC + kc * BK + kv * 8;
            cpa16(sAu + soff, ga);
            cpa16(sBu + soff, gb);
        }
        cpa_commit();
    };

    const int wm = (w & 3) * 32, wn = (w >> 2) * 64;

    float acc[2][8][4];
#pragma unroll
    for (int mt = 0; mt < 2; ++mt)
#pragma unroll
        for (int nt = 0; nt < 8; ++nt)
#pragma unroll
            for (int q = 0; q < 4; ++q) acc[mt][nt][q] = 0.f;

    uint32_t aBase[NSTG], bBase[NSTG];
    {
        int ar = wm + (lane & 15);
        int ak = (lane >> 4) * 8;
        int i = lane >> 3, r = lane & 7;
        int br = wn + (i >> 1) * 8 + r;
        int bk = (i & 1) * 8;
#pragma unroll
        for (int s = 0; s < NSTG; ++s) {
            aBase[s] = sm2u(&sA[s * STG_HALVES + ar * PAD + ak]);
            bBase[s] = sm2u(&sB[s * STG_HALVES + br * PAD + bk]);
        }
    }

    stage_load(0);
    stage_load(1);

    for (int kc = 0; kc < NK; ++kc) {
        const int cur = kc % NSTG;
        CPA_WAIT(1);          // chunk kc resident
        __syncthreads();
        if (kc + 2 < NK) stage_load(kc + 2);
        else cpa_commit();
#pragma unroll
        for (int kk = 0; kk < 4; ++kk) {
            uint32_t af[2][4], bf[4][4];
#pragma unroll
            for (int mt = 0; mt < 2; ++mt)
                ldsm4(af[mt], aBase[cur] + (uint32_t)((mt * 16 * PAD + kk * 16) * 2));
#pragma unroll
            for (int nn = 0; nn < 4; ++nn)
                ldsm4(bf[nn], bBase[cur] + (uint32_t)((nn * 16 * PAD + kk * 16) * 2));
#pragma unroll
            for (int mt = 0; mt < 2; ++mt)
#pragma unroll
                for (int nt = 0; nt < 8; ++nt) {
                    int nn = nt >> 1, sel = (nt & 1) * 2;
                    mma16816(acc[mt][nt], af[mt], bf[nn][sel], bf[nn][sel + 1]);
                }
        }
    }
    CPA_WAIT(0);
    __syncthreads();    // all ldsm reads done before smem reuse as epilogue tile

    // ---- epilogue: e = exp2(sim*log2e) -> etile; row/col sums of e (no smem atomics) ----
    __half* etile = reinterpret_cast<__half*>(smbuf);                 // 128 x EPAD halves (34816B)
    float* csPart = reinterpret_cast<float*>(smbuf + 36864);          // [4][TILE] partials
    const int gID = lane >> 2, tig = lane & 3;
    const int wmg = w & 3;
    float rsum[2][2] = {{0.f, 0.f}, {0.f, 0.f}};

#pragma unroll
    for (int nt = 0; nt < 8; ++nt) {
        const int lcol = wn + nt * 8 + tig * 2;
        const bool cv = (tn * TILE + lcol) < SS;
        float cs0 = 0.f, cs1 = 0.f;
#pragma unroll
        for (int mt = 0; mt < 2; ++mt)
#pragma unroll
            for (int h = 0; h < 2; ++h) {
                const int lrow = wm + mt * 16 + h * 8 + gID;
                const bool rvd = (tm * TILE + lrow) < LL;
                float e0 = cv ? exp2f(acc[mt][nt][h * 2 + 0] * EX2SC) : 0.f;
                float e1 = cv ? exp2f(acc[mt][nt][h * 2 + 1] * EX2SC) : 0.f;
                rsum[mt][h] += e0 + e1;
                if (rvd) { cs0 += e0; cs1 += e1; }
                __half2 st = __floats2half2_rn(e0, e1);
                *reinterpret_cast<__half2*>(etile + lrow * EPAD + lcol) = st;
            }
        cs0 += __shfl_xor_sync(0xffffffffu, cs0, 4);
        cs0 += __shfl_xor_sync(0xffffffffu, cs0, 8);
        cs0 += __shfl_xor_sync(0xffffffffu, cs0, 16);
        cs1 += __shfl_xor_sync(0xffffffffu, cs1, 4);
        cs1 += __shfl_xor_sync(0xffffffffu, cs1, 8);
        cs1 += __shfl_xor_sync(0xffffffffu, cs1, 16);
        if (gID == 0) {   // unique (wmg, col) per store — plain STS, no atomics
            csPart[wmg * TILE + lcol] = cs0;
            csPart[wmg * TILE + lcol + 1] = cs1;
        }
    }
#pragma unroll
    for (int mt = 0; mt < 2; ++mt)
#pragma unroll
        for (int h = 0; h < 2; ++h) {
            float r = rsum[mt][h];
            r += __shfl_xor_sync(0xffffffffu, r, 1);
            r += __shfl_xor_sync(0xffffffffu, r, 2);
            const int row = tm * TILE + wm + mt * 16 + h * 8 + gID;
            if (tig == 0 && row < LL) atomicAdd(&g_R[nb * LL + row], r);
        }
    __syncthreads();

    // coalesced e tile store: 2048 16B-chunks, 8 per thread. st.cg keeps e in L2
    // for the conf pass that re-reads it ~25us later (no evict-first).
#pragma unroll
    for (int q = 0; q < 8; ++q) {
        int idx = tid + q * 256;           // 0..2047
        int r = idx >> 4, c16 = idx & 15;  // row 0..127, 16B chunk 0..15
        int grow = tm * TILE + r;
        int gcol = tn * TILE + c16 * 8;    // 8 halves per chunk; SS % 8 == 0
        if (grow < LL && gcol < SS) {
            float4 v = *reinterpret_cast<const float4*>(etile + r * EPAD + c16 * 8);
            __stcg(reinterpret_cast<float4*>(g_E + ((size_t)nb * LL + grow) * SS + gcol), v);
        }
    }

    if (tid < TILE) {
        int col = tn * TILE + tid;
        if (col < SS) {
            float s = csPart[tid] + csPart[TILE + tid] +
                      csPart[2 * TILE + tid] + csPart[3 * TILE + tid];
            atomicAdd(&g_Cs[nb * SS + col], s);
        }
    }
}

// ---------------- conf = e*e*(1/R)*iC -> out (one batch), track row max ----------------
__global__ void __launch_bounds__(256) conf_kernel(float* __restrict__ out, int nb) {
    const int row = nb * LL + blockIdx.x;   // global row
    const float ir = __frcp_rn(g_R[row]);
    const __half* ep = g_E + (size_t)row * SS;
    float* rowp = out + (size_t)row * SS;
    const float* icp = g_iC + nb * SS;
    float rmax = 0.f;
    for (int c = threadIdx.x * 4; c < SS; c += blockDim.x * 4) {
        uint2 hraw = __ldcg(reinterpret_cast<const uint2*>(ep + c));   // L2 hit path
        float4 ic = *reinterpret_cast<const float4*>(icp + c);
        float2 h01 = __half22float2(*reinterpret_cast<const __half2*>(&hraw.x));
        float2 h23 = __half22float2(*reinterpret_cast<const __half2*>(&hraw.y));
        float4 q;
        q.x = h01.x * h01.x * ir * ic.x;
        q.y = h01.y * h01.y * ir * ic.y;
        q.z = h23.x * h23.x * ir * ic.z;
        q.w = h23.y * h23.y * ir * ic.w;
        __stcs(reinterpret_cast<float4*>(rowp + c), q);
        rmax = fmaxf(fmaxf(rmax, q.x), fmaxf(q.y, fmaxf(q.z, q.w)));
    }
#pragma unroll
    for (int off = 16; off; off >>= 1)
        rmax = fmaxf(rmax, __shfl_xor_sync(0xffffffffu, rmax, off));
    if ((threadIdx.x & 31) == 0)
        atomicMax(reinterpret_cast<int*>(&g_RM[row]), __float_as_int(rmax));
}

// ---------------- match extraction (expected no-op: conf << THR) ----------------
__global__ void match_kernel(float* __restrict__ out, long long out_size) {
    int r = blockIdx.x * blockDim.x + threadIdx.x;
    if (r >= NB * LL) return;
    long long NLS = (long long)NB * LL * SS;
    if (out_size < NLS + (long long)3 * NB * LL + NB) return;
    float rm = g_RM[r];
    if (!(rm > THRV)) return;
    int nb = r / LL;
    const float* crow = out + (size_t)r * SS;
    for (int s = 0; s < SS; ++s) {
        if (crow[s] == rm) {
            bool ismax = true;
            for (int l2 = 0; l2 < LL; ++l2)
                if (out[((size_t)nb * LL + l2) * SS + s] > rm) { ismax = false; break; }
            if (ismax) {
                out[NLS + r] = 1.0f;
                out[NLS + (long long)NB * LL + r] = (float)s;
                out[NLS + (long long)2 * NB * LL + r] = rm;
                atomicAdd(&out[NLS + (long long)3 * NB * LL + nb], 1.0f);
                return;
            }
        }
    }
}

// ---------------- launch ----------------
extern "C" void kernel_launch(void* const* d_in, const int* in_sizes, int n_in,
                              void* d_out, int out_size) {
    const float* f0 = (const float*)d_in[0];
    const float* f1 = (const float*)d_in[1];
    float* out = (float*)d_out;
    long long osz = (long long)out_size;

    // one-time host objects (no device memory); same device work every call
    static cudaStream_t s_fork = nullptr;
    static cudaEvent_t s_ev0 = nullptr, s_evA = nullptr, s_evB = nullptr, s_evP1 = nullptr;
    if (s_fork == nullptr) {
        cudaStreamCreateWithFlags(&s_fork, cudaStreamNonBlocking);
        cudaEventCreateWithFlags(&s_ev0, cudaEventDisableTiming);
        cudaEventCreateWithFlags(&s_evA, cudaEventDisableTiming);
        cudaEventCreateWithFlags(&s_evB, cudaEventDisableTiming);
        cudaEventCreateWithFlags(&s_evP1, cudaEventDisableTiming);
        cudaFuncSetAttribute(gemm_kernel, cudaFuncAttributeMaxDynamicSharedMemorySize, SM_STAGES);
    }

    unsigned pgrid = (unsigned)((LPAD * CC / 4 + 255) / 256);
    dim3 grid(NT, NT);

    // fork origin: s_fork joins capture by waiting on a main-stream event first
    cudaEventRecord(s_ev0, 0);
    cudaStreamWaitEvent(s_fork, s_ev0, 0);

    // fork: prep batch 1 concurrently with main-stream prep(0)+gemm(0)
    prep_kernel<<<pgrid, 256, 0, s_fork>>>(f0, f1, out, osz, 1);
    cudaEventRecord(s_evP1, s_fork);

    prep_kernel<<<pgrid, 256>>>(f0, f1, out, osz, 0);
    gemm_kernel<<<grid, 256, SM_STAGES>>>(0);
    cudaEventRecord(s_evA, 0);                 // batch-0 sums/e complete

    cudaStreamWaitEvent(0, s_evP1, 0);
    gemm_kernel<<<grid, 256, SM_STAGES>>>(1);  // main: batch-1 GEMM

    cudaStreamWaitEvent(s_fork, s_evA, 0);     // fork: conf batch 0 overlaps gemm batch 1
    recip_kernel<<<(SS + 255) / 256, 256, 0, s_fork>>>(0);
    conf_kernel<<<LL, 256, 0, s_fork>>>(out, 0);
    cudaEventRecord(s_evB, s_fork);

    recip_kernel<<<(SS + 255) / 256, 256>>>(1);
    conf_kernel<<<LL, 256>>>(out, 1);          // main stream, after gemm(1)
    cudaStreamWaitEvent(0, s_evB, 0);          // join fork before match
    match_kernel<<<(NB * LL + 255) / 256, 256>>>(out, osz);
}

// round 15
// speedup vs baseline: 1.0246x; 1.0246x over previous
#include <cuda_runtime.h>
#include <cuda_fp16.h>
#include <cstdint>

// CoarseMatching: N=2, L=S=4800, C=256
#define NB 2
#define LL 4800
#define SS 4800
#define CC 256
#define TILE 128
#define NT ((LL + TILE - 1) / TILE)   // 38
#define LPAD (NT * TILE)              // 4864 padded rows
#define BK 64
#define NK (CC / BK)                  // 4
#define PAD 72                        // smem row stride in halves (144B) for BK=64
#define STG_HALVES (TILE * PAD)       // 9216 halves = 18432 B per stage per array
#define STG_BYTES (STG_HALVES * 2)
#define NSTG 3
#define EPAD 136                      // epilogue smem tile row stride in halves (272B)
#define SM_STAGES (2 * NSTG * STG_BYTES)   // 110592 — epilogue tile + csPart overlay inside
#define EX2SC 0.05635527504843507f    // (1/(256*0.1)) * log2(e)
#define THRV 0.2f

// ---------------- device scratch ----------------
__device__ __half g_h0[NB * LPAD * CC];
__device__ __half g_h1[NB * LPAD * CC];
__device__ __half g_E [(size_t)NB * LL * SS];  // e = exp(sim), fp16 (92 MB)
__device__ float  g_R [NB * LL];   // row sums of exp(sim)
__device__ float  g_Cs[NB * SS];   // col sums of exp(sim)
__device__ float  g_iC[NB * SS];   // 1/colsum
__device__ float  g_RM[NB * LL];   // per-row max of conf

// ---------------- PTX helpers ----------------
__device__ __forceinline__ uint32_t sm2u(const void* p) {
    uint32_t a;
    asm("{ .reg .u64 t; cvta.to.shared.u64 t, %1; cvt.u32.u64 %0, t; }" : "=r"(a) : "l"(p));
    return a;
}

__device__ __forceinline__ void ldsm4(uint32_t* r, uint32_t addr) {
    asm volatile("ldmatrix.sync.aligned.m8n8.x4.shared.b16 {%0,%1,%2,%3}, [%4];"
                 : "=r"(r[0]), "=r"(r[1]), "=r"(r[2]), "=r"(r[3]) : "r"(addr));
}

__device__ __forceinline__ void mma16816(float* d, const uint32_t* a, uint32_t b0, uint32_t b1) {
    asm volatile(
        "mma.sync.aligned.m16n8k16.row.col.f32.f16.f16.f32 "
        "{%0,%1,%2,%3}, {%4,%5,%6,%7}, {%8,%9}, {%0,%1,%2,%3};"
        : "+f"(d[0]), "+f"(d[1]), "+f"(d[2]), "+f"(d[3])
        : "r"(a[0]), "r"(a[1]), "r"(a[2]), "r"(a[3]), "r"(b0), "r"(b1));
}

__device__ __forceinline__ void cpa16(uint32_t smem, const void* gmem) {
    asm volatile("cp.async.cg.shared.global [%0], [%1], 16;" :: "r"(smem), "l"(gmem));
}
__device__ __forceinline__ void cpa_commit() {
    asm volatile("cp.async.commit_group;" ::: "memory");
}
#define CPA_WAIT(n) asm volatile("cp.async.wait_group %0;" :: "n"(n) : "memory")

// ---------------- prep (one batch): fp32 -> fp16 with zero padding; nb==0 also zeros ----------------
__global__ void prep_kernel(const float* __restrict__ f0, const float* __restrict__ f1,
                            float* __restrict__ out, long long out_size, int nb) {
    long long i = (long long)blockIdx.x * blockDim.x + threadIdx.x;   // one uint2 (4 halves)
    if (nb == 0) {
        if (i < NB * LL) { g_R[i] = 0.f; g_RM[i] = 0.f; }
        if (i < NB * SS) g_Cs[i] = 0.f;
        long long NLS = (long long)NB * LL * SS;
        long long extras = (long long)3 * NB * LL + NB;
        if (out_size >= NLS + extras && i < extras) out[NLS + i] = 0.f;
    }
    long long n4 = (long long)LPAD * CC / 4;       // per batch
    if (i >= n4) return;
    long long t = i * 4;
    int row = (int)(t / CC), c = (int)(t % CC);
    uint2 z0 = make_uint2(0u, 0u), z1 = make_uint2(0u, 0u);
    if (row < LL) {
        long long s = ((long long)nb * LL + row) * CC + c;
        float4 a = *reinterpret_cast<const float4*>(f0 + s);
        float4 b = *reinterpret_cast<const float4*>(f1 + s);
        __half2 a01 = __floats2half2_rn(a.x, a.y), a23 = __floats2half2_rn(a.z, a.w);
        __half2 b01 = __floats2half2_rn(b.x, b.y), b23 = __floats2half2_rn(b.z, b.w);
        z0 = make_uint2(*(uint32_t*)&a01, *(uint32_t*)&a23);
        z1 = make_uint2(*(uint32_t*)&b01, *(uint32_t*)&b23);
    }
    long long base = (long long)nb * LPAD * CC / 4;
    reinterpret_cast<uint2*>(g_h0)[base + i] = z0;
    reinterpret_cast<uint2*>(g_h1)[base + i] = z1;
}

__global__ void recip_kernel(int nb) {
    int i = blockIdx.x * blockDim.x + threadIdx.x;
    if (i < SS) g_iC[nb * SS + i] = __frcp_rn(g_Cs[nb * SS + i]);
}

// ---------------- GEMM (one batch): e = exp(sim) -> g_E (fp16); row/col sums of e ----------------
__global__ void __launch_bounds__(256, 2) gemm_kernel(int nb) {
    extern __shared__ __align__(16) char smbuf[];
    __half* sA = reinterpret_cast<__half*>(smbuf);
    __half* sB = reinterpret_cast<__half*>(smbuf + NSTG * STG_BYTES);

    const int tid = threadIdx.x, lane = tid & 31, w = tid >> 5;
    const int tn = blockIdx.x, tm = blockIdx.y;

    const __half* A = g_h0 + (size_t)nb * LPAD * CC + (size_t)tm * TILE * CC;
    const __half* B = g_h1 + (size_t)nb * LPAD * CC + (size_t)tn * TILE * CC;

    const uint32_t sAu = sm2u(sA), sBu = sm2u(sB);

    // per chunk: 128 rows x 64 halves (128B) per array -> 1024 16B-vectors, 4/thread/array
    auto stage_load = [&](int kc) {
        int st = kc % NSTG;
#pragma unroll
        for (int h = 0; h < 4; ++h) {
            int v = tid + h * 256;            // 0..1023
            int row = v >> 3, kv = v & 7;     // row 0..127, 16B chunk 0..7
            uint32_t soff = (uint32_t)st * STG_BYTES + (uint32_t)((row * PAD + kv * 8) * 2);
            const __half* ga = A + (size_t)row * CC + kc * BK + kv * 8;
            const __half* gb = B + (size_t)row * CC + kc * BK + kv * 8;
            cpa16(sAu + soff, ga);
            cpa16(sBu + soff, gb);
        }
        cpa_commit();
    };

    const int wm = (w & 3) * 32, wn = (w >> 2) * 64;

    float acc[2][8][4];
#pragma unroll
    for (int mt = 0; mt < 2; ++mt)
#pragma unroll
        for (int nt = 0; nt < 8; ++nt)
#pragma unroll
            for (int q = 0; q < 4; ++q) acc[mt][nt][q] = 0.f;

    uint32_t aBase[NSTG], bBase[NSTG];
    {
        int ar = wm + (lane & 15);
        int ak = (lane >> 4) * 8;
        int i = lane >> 3, r = lane & 7;
        int br = wn + (i >> 1) * 8 + r;
        int bk = (i & 1) * 8;
#pragma unroll
        for (int s = 0; s < NSTG; ++s) {
            aBase[s] = sm2u(&sA[s * STG_HALVES + ar * PAD + ak]);
            bBase[s] = sm2u(&sB[s * STG_HALVES + br * PAD + bk]);
        }
    }

    stage_load(0);
    stage_load(1);

    for (int kc = 0; kc < NK; ++kc) {
        const int cur = kc % NSTG;
        CPA_WAIT(1);          // chunk kc resident
        __syncthreads();
        if (kc + 2 < NK) stage_load(kc + 2);
        else cpa_commit();
#pragma unroll
        for (int kk = 0; kk < 4; ++kk) {
            uint32_t af[2][4], bf[4][4];
#pragma unroll
            for (int mt = 0; mt < 2; ++mt)
                ldsm4(af[mt], aBase[cur] + (uint32_t)((mt * 16 * PAD + kk * 16) * 2));
#pragma unroll
            for (int nn = 0; nn < 4; ++nn)
                ldsm4(bf[nn], bBase[cur] + (uint32_t)((nn * 16 * PAD + kk * 16) * 2));
#pragma unroll
            for (int mt = 0; mt < 2; ++mt)
#pragma unroll
                for (int nt = 0; nt < 8; ++nt) {
                    int nn = nt >> 1, sel = (nt & 1) * 2;
                    mma16816(acc[mt][nt], af[mt], bf[nn][sel], bf[nn][sel + 1]);
                }
        }
    }
    CPA_WAIT(0);
    __syncthreads();    // all ldsm reads done before smem reuse as epilogue tile

    // ---- epilogue: e = exp2(sim*log2e) -> etile; row/col sums of e (no smem atomics) ----
    __half* etile = reinterpret_cast<__half*>(smbuf);                 // 128 x EPAD halves (34816B)
    float* csPart = reinterpret_cast<float*>(smbuf + 36864);          // [4][TILE] partials
    const int gID = lane >> 2, tig = lane & 3;
    const int wmg = w & 3;
    float rsum[2][2] = {{0.f, 0.f}, {0.f, 0.f}};

#pragma unroll
    for (int nt = 0; nt < 8; ++nt) {
        const int lcol = wn + nt * 8 + tig * 2;
        const bool cv = (tn * TILE + lcol) < SS;
        float cs0 = 0.f, cs1 = 0.f;
#pragma unroll
        for (int mt = 0; mt < 2; ++mt)
#pragma unroll
            for (int h = 0; h < 2; ++h) {
                const int lrow = wm + mt * 16 + h * 8 + gID;
                const bool rvd = (tm * TILE + lrow) < LL;
                float e0 = cv ? exp2f(acc[mt][nt][h * 2 + 0] * EX2SC) : 0.f;
                float e1 = cv ? exp2f(acc[mt][nt][h * 2 + 1] * EX2SC) : 0.f;
                rsum[mt][h] += e0 + e1;
                if (rvd) { cs0 += e0; cs1 += e1; }
                __half2 st = __floats2half2_rn(e0, e1);
                *reinterpret_cast<__half2*>(etile + lrow * EPAD + lcol) = st;
            }
        cs0 += __shfl_xor_sync(0xffffffffu, cs0, 4);
        cs0 += __shfl_xor_sync(0xffffffffu, cs0, 8);
        cs0 += __shfl_xor_sync(0xffffffffu, cs0, 16);
        cs1 += __shfl_xor_sync(0xffffffffu, cs1, 4);
        cs1 += __shfl_xor_sync(0xffffffffu, cs1, 8);
        cs1 += __shfl_xor_sync(0xffffffffu, cs1, 16);
        if (gID == 0) {   // unique (wmg, col) per store — plain STS, no atomics
            csPart[wmg * TILE + lcol] = cs0;
            csPart[wmg * TILE + lcol + 1] = cs1;
        }
    }
#pragma unroll
    for (int mt = 0; mt < 2; ++mt)
#pragma unroll
        for (int h = 0; h < 2; ++h) {
            float r = rsum[mt][h];
            r += __shfl_xor_sync(0xffffffffu, r, 1);
            r += __shfl_xor_sync(0xffffffffu, r, 2);
            const int row = tm * TILE + wm + mt * 16 + h * 8 + gID;
            if (tig == 0 && row < LL) atomicAdd(&g_R[nb * LL + row], r);
        }
    __syncthreads();

    // coalesced e tile store: 2048 16B-chunks, 8 per thread (streaming — R14 showed
    // st.cg L2-retention does NOT pay; evict-first is better here)
#pragma unroll
    for (int q = 0; q < 8; ++q) {
        int idx = tid + q * 256;           // 0..2047
        int r = idx >> 4, c16 = idx & 15;  // row 0..127, 16B chunk 0..15
        int grow = tm * TILE + r;
        int gcol = tn * TILE + c16 * 8;    // 8 halves per chunk; SS % 8 == 0
        if (grow < LL && gcol < SS) {
            float4 v = *reinterpret_cast<const float4*>(etile + r * EPAD + c16 * 8);
            __stcs(reinterpret_cast<float4*>(g_E + ((size_t)nb * LL + grow) * SS + gcol), v);
        }
    }

    if (tid < TILE) {
        int col = tn * TILE + tid;
        if (col < SS) {
            float s = csPart[tid] + csPart[TILE + tid] +
                      csPart[2 * TILE + tid] + csPart[3 * TILE + tid];
            atomicAdd(&g_Cs[nb * SS + col], s);
        }
    }
}

// ---------------- conf = e*e*(1/R)*iC -> out (one batch), track row max ----------------
__global__ void __launch_bounds__(256) conf_kernel(float* __restrict__ out, int nb) {
    const int row = nb * LL + blockIdx.x;   // global row
    const float ir = __frcp_rn(g_R[row]);
    const __half* ep = g_E + (size_t)row * SS;
    float* rowp = out + (size_t)row * SS;
    const float* icp = g_iC + nb * SS;
    float rmax = 0.f;
    for (int c = threadIdx.x * 4; c < SS; c += blockDim.x * 4) {
        uint2 hraw = __ldcs(reinterpret_cast<const uint2*>(ep + c));
        float4 ic = *reinterpret_cast<const float4*>(icp + c);
        float2 h01 = __half22float2(*reinterpret_cast<const __half2*>(&hraw.x));
        float2 h23 = __half22float2(*reinterpret_cast<const __half2*>(&hraw.y));
        float4 q;
        q.x = h01.x * h01.x * ir * ic.x;
        q.y = h01.y * h01.y * ir * ic.y;
        q.z = h23.x * h23.x * ir * ic.z;
        q.w = h23.y * h23.y * ir * ic.w;
        __stcs(reinterpret_cast<float4*>(rowp + c), q);
        rmax = fmaxf(fmaxf(rmax, q.x), fmaxf(q.y, fmaxf(q.z, q.w)));
    }
#pragma unroll
    for (int off = 16; off; off >>= 1)
        rmax = fmaxf(rmax, __shfl_xor_sync(0xffffffffu, rmax, off));
    if ((threadIdx.x & 31) == 0)
        atomicMax(reinterpret_cast<int*>(&g_RM[row]), __float_as_int(rmax));
}

// ---------------- match extraction, one batch (expected no-op: conf << THR) ----------------
__global__ void match_kernel(float* __restrict__ out, long long out_size, int nb) {
    int rr = blockIdx.x * blockDim.x + threadIdx.x;
    if (rr >= LL) return;
    int r = nb * LL + rr;
    long long NLS = (long long)NB * LL * SS;
    if (out_size < NLS + (long long)3 * NB * LL + NB) return;
    float rm = g_RM[r];
    if (!(rm > THRV)) return;
    const float* crow = out + (size_t)r * SS;
    for (int s = 0; s < SS; ++s) {
        if (crow[s] == rm) {
            bool ismax = true;
            for (int l2 = 0; l2 < LL; ++l2)
                if (out[((size_t)nb * LL + l2) * SS + s] > rm) { ismax = false; break; }
            if (ismax) {
                out[NLS + r] = 1.0f;
                out[NLS + (long long)NB * LL + r] = (float)s;
                out[NLS + (long long)2 * NB * LL + r] = rm;
                atomicAdd(&out[NLS + (long long)3 * NB * LL + nb], 1.0f);
                return;
            }
        }
    }
}

// ---------------- launch ----------------
extern "C" void kernel_launch(void* const* d_in, const int* in_sizes, int n_in,
                              void* d_out, int out_size) {
    const float* f0 = (const float*)d_in[0];
    const float* f1 = (const float*)d_in[1];
    float* out = (float*)d_out;
    long long osz = (long long)out_size;

    // one-time host objects (no device memory); same device work every call
    static cudaStream_t s_fork = nullptr;
    static cudaEvent_t s_ev0 = nullptr, s_evA = nullptr, s_evB = nullptr, s_evP1 = nullptr;
    if (s_fork == nullptr) {
        cudaStreamCreateWithFlags(&s_fork, cudaStreamNonBlocking);
        cudaEventCreateWithFlags(&s_ev0, cudaEventDisableTiming);
        cudaEventCreateWithFlags(&s_evA, cudaEventDisableTiming);
        cudaEventCreateWithFlags(&s_evB, cudaEventDisableTiming);
        cudaEventCreateWithFlags(&s_evP1, cudaEventDisableTiming);
        cudaFuncSetAttribute(gemm_kernel, cudaFuncAttributeMaxDynamicSharedMemorySize, SM_STAGES);
    }

    unsigned pgrid = (unsigned)((LPAD * CC / 4 + 255) / 256);
    dim3 grid(NT, NT);

    // fork origin: s_fork joins capture by waiting on a main-stream event first
    cudaEventRecord(s_ev0, 0);
    cudaStreamWaitEvent(s_fork, s_ev0, 0);

    // fork: prep batch 1 concurrently with main-stream prep(0)+gemm(0)
    prep_kernel<<<pgrid, 256, 0, s_fork>>>(f0, f1, out, osz, 1);
    cudaEventRecord(s_evP1, s_fork);

    prep_kernel<<<pgrid, 256>>>(f0, f1, out, osz, 0);
    gemm_kernel<<<grid, 256, SM_STAGES>>>(0);
    cudaEventRecord(s_evA, 0);                 // batch-0 sums/e complete

    cudaStreamWaitEvent(0, s_evP1, 0);
    gemm_kernel<<<grid, 256, SM_STAGES>>>(1);  // main: batch-1 GEMM

    cudaStreamWaitEvent(s_fork, s_evA, 0);     // fork: batch-0 postprocess overlaps gemm(1)
    recip_kernel<<<(SS + 255) / 256, 256, 0, s_fork>>>(0);
    conf_kernel<<<LL, 256, 0, s_fork>>>(out, 0);
    match_kernel<<<(LL + 255) / 256, 256, 0, s_fork>>>(out, osz, 0);
    cudaEventRecord(s_evB, s_fork);

    recip_kernel<<<(SS + 255) / 256, 256>>>(1);
    conf_kernel<<<LL, 256>>>(out, 1);          // main stream, after gemm(1)
    match_kernel<<<(LL + 255) / 256, 256>>>(out, osz, 1);
    cudaStreamWaitEvent(0, s_evB, 0);          // join fork at the very end
}

// round 16
// speedup vs baseline: 1.0383x; 1.0134x over previous
#include <cuda_runtime.h>
#include <cuda_fp16.h>
#include <cstdint>

// CoarseMatching: N=2, L=S=4800, C=256
#define NB 2
#define LL 4800
#define SS 4800
#define CC 256
#define TILE 128
#define NT ((LL + TILE - 1) / TILE)   // 38
#define LPAD (NT * TILE)              // 4864 padded rows
#define BK 64
#define NK (CC / BK)                  // 4
#define PAD 72                        // smem row stride in halves (144B) for BK=64
#define STG_HALVES (TILE * PAD)       // 9216 halves = 18432 B per stage per array
#define STG_BYTES (STG_HALVES * 2)
#define NSTG 3
#define EPAD 136                      // epilogue smem tile row stride in halves (272B)
#define SM_STAGES (2 * NSTG * STG_BYTES)   // 110592 — epilogue tile + csPart overlay inside
#define EX2SC 0.05635527504843507f    // (1/(256*0.1)) * log2(e)
#define THRV 0.2f

// ---------------- device scratch ----------------
__device__ __half g_h0[NB * LPAD * CC];
__device__ __half g_h1[NB * LPAD * CC];
__device__ __half g_E [(size_t)NB * LL * SS];  // e = exp(sim), fp16 (92 MB)
__device__ float  g_R [NB * LL];   // row sums of exp(sim)
__device__ float  g_Cs[NB * SS];   // col sums of exp(sim)
__device__ float  g_iC[NB * SS];   // 1/colsum

// ---------------- PTX helpers ----------------
__device__ __forceinline__ uint32_t sm2u(const void* p) {
    uint32_t a;
    asm("{ .reg .u64 t; cvta.to.shared.u64 t, %1; cvt.u32.u64 %0, t; }" : "=r"(a) : "l"(p));
    return a;
}

__device__ __forceinline__ void ldsm4(uint32_t* r, uint32_t addr) {
    asm volatile("ldmatrix.sync.aligned.m8n8.x4.shared.b16 {%0,%1,%2,%3}, [%4];"
                 : "=r"(r[0]), "=r"(r[1]), "=r"(r[2]), "=r"(r[3]) : "r"(addr));
}

__device__ __forceinline__ void mma16816(float* d, const uint32_t* a, uint32_t b0, uint32_t b1) {
    asm volatile(
        "mma.sync.aligned.m16n8k16.row.col.f32.f16.f16.f32 "
        "{%0,%1,%2,%3}, {%4,%5,%6,%7}, {%8,%9}, {%0,%1,%2,%3};"
        : "+f"(d[0]), "+f"(d[1]), "+f"(d[2]), "+f"(d[3])
        : "r"(a[0]), "r"(a[1]), "r"(a[2]), "r"(a[3]), "r"(b0), "r"(b1));
}

__device__ __forceinline__ void cpa16(uint32_t smem, const void* gmem) {
    asm volatile("cp.async.cg.shared.global [%0], [%1], 16;" :: "r"(smem), "l"(gmem));
}
__device__ __forceinline__ void cpa_commit() {
    asm volatile("cp.async.commit_group;" ::: "memory");
}
#define CPA_WAIT(n) asm volatile("cp.async.wait_group %0;" :: "n"(n) : "memory")

// ---------------- prep (one batch): fp32 -> fp16 with zero padding; nb==0 also zeros ----------------
__global__ void prep_kernel(const float* __restrict__ f0, const float* __restrict__ f1,
                            float* __restrict__ out, long long out_size, int nb) {
    long long i = (long long)blockIdx.x * blockDim.x + threadIdx.x;   // one uint2 (4 halves)
    if (nb == 0) {
        if (i < NB * LL) g_R[i] = 0.f;
        if (i < NB * SS) g_Cs[i] = 0.f;
        long long NLS = (long long)NB * LL * SS;
        long long extras = (long long)3 * NB * LL + NB;
        if (out_size >= NLS + extras && i < extras) out[NLS + i] = 0.f;
    }
    long long n4 = (long long)LPAD * CC / 4;       // per batch
    if (i >= n4) return;
    long long t = i * 4;
    int row = (int)(t / CC), c = (int)(t % CC);
    uint2 z0 = make_uint2(0u, 0u), z1 = make_uint2(0u, 0u);
    if (row < LL) {
        long long s = ((long long)nb * LL + row) * CC + c;
        float4 a = *reinterpret_cast<const float4*>(f0 + s);
        float4 b = *reinterpret_cast<const float4*>(f1 + s);
        __half2 a01 = __floats2half2_rn(a.x, a.y), a23 = __floats2half2_rn(a.z, a.w);
        __half2 b01 = __floats2half2_rn(b.x, b.y), b23 = __floats2half2_rn(b.z, b.w);
        z0 = make_uint2(*(uint32_t*)&a01, *(uint32_t*)&a23);
        z1 = make_uint2(*(uint32_t*)&b01, *(uint32_t*)&b23);
    }
    long long base = (long long)nb * LPAD * CC / 4;
    reinterpret_cast<uint2*>(g_h0)[base + i] = z0;
    reinterpret_cast<uint2*>(g_h1)[base + i] = z1;
}

__global__ void recip_kernel(int nb) {
    int i = blockIdx.x * blockDim.x + threadIdx.x;
    if (i < SS) g_iC[nb * SS + i] = __frcp_rn(g_Cs[nb * SS + i]);
}

// ---------------- GEMM (one batch): e = exp(sim) -> g_E (fp16); row/col sums of e ----------------
__global__ void __launch_bounds__(256, 2) gemm_kernel(int nb) {
    extern __shared__ __align__(16) char smbuf[];
    __half* sA = reinterpret_cast<__half*>(smbuf);
    __half* sB = reinterpret_cast<__half*>(smbuf + NSTG * STG_BYTES);

    const int tid = threadIdx.x, lane = tid & 31, w = tid >> 5;
    const int tn = blockIdx.x, tm = blockIdx.y;

    const __half* A = g_h0 + (size_t)nb * LPAD * CC + (size_t)tm * TILE * CC;
    const __half* B = g_h1 + (size_t)nb * LPAD * CC + (size_t)tn * TILE * CC;

    const uint32_t sAu = sm2u(sA), sBu = sm2u(sB);

    // per chunk: 128 rows x 64 halves (128B) per array -> 1024 16B-vectors, 4/thread/array
    auto stage_load = [&](int kc) {
        int st = kc % NSTG;
#pragma unroll
        for (int h = 0; h < 4; ++h) {
            int v = tid + h * 256;            // 0..1023
            int row = v >> 3, kv = v & 7;     // row 0..127, 16B chunk 0..7
            uint32_t soff = (uint32_t)st * STG_BYTES + (uint32_t)((row * PAD + kv * 8) * 2);
            const __half* ga = A + (size_t)row * CC + kc * BK + kv * 8;
            const __half* gb = B + (size_t)row * CC + kc * BK + kv * 8;
            cpa16(sAu + soff, ga);
            cpa16(sBu + soff, gb);
        }
        cpa_commit();
    };

    const int wm = (w & 3) * 32, wn = (w >> 2) * 64;

    float acc[2][8][4];
#pragma unroll
    for (int mt = 0; mt < 2; ++mt)
#pragma unroll
        for (int nt = 0; nt < 8; ++nt)
#pragma unroll
            for (int q = 0; q < 4; ++q) acc[mt][nt][q] = 0.f;

    uint32_t aBase[NSTG], bBase[NSTG];
    {
        int ar = wm + (lane & 15);
        int ak = (lane >> 4) * 8;
        int i = lane >> 3, r = lane & 7;
        int br = wn + (i >> 1) * 8 + r;
        int bk = (i & 1) * 8;
#pragma unroll
        for (int s = 0; s < NSTG; ++s) {
            aBase[s] = sm2u(&sA[s * STG_HALVES + ar * PAD + ak]);
            bBase[s] = sm2u(&sB[s * STG_HALVES + br * PAD + bk]);
        }
    }

    stage_load(0);
    stage_load(1);

    for (int kc = 0; kc < NK; ++kc) {
        const int cur = kc % NSTG;
        CPA_WAIT(1);          // chunk kc resident
        __syncthreads();
        if (kc + 2 < NK) stage_load(kc + 2);
        else cpa_commit();
#pragma unroll
        for (int kk = 0; kk < 4; ++kk) {
            uint32_t af[2][4], bf[4][4];
#pragma unroll
            for (int mt = 0; mt < 2; ++mt)
                ldsm4(af[mt], aBase[cur] + (uint32_t)((mt * 16 * PAD + kk * 16) * 2));
#pragma unroll
            for (int nn = 0; nn < 4; ++nn)
                ldsm4(bf[nn], bBase[cur] + (uint32_t)((nn * 16 * PAD + kk * 16) * 2));
#pragma unroll
            for (int mt = 0; mt < 2; ++mt)
#pragma unroll
                for (int nt = 0; nt < 8; ++nt) {
                    int nn = nt >> 1, sel = (nt & 1) * 2;
                    mma16816(acc[mt][nt], af[mt], bf[nn][sel], bf[nn][sel + 1]);
                }
        }
    }
    CPA_WAIT(0);
    __syncthreads();    // all ldsm reads done before smem reuse as epilogue tile

    // ---- epilogue: e = exp2(sim*log2e) -> etile; row/col sums of e (no smem atomics) ----
    __half* etile = reinterpret_cast<__half*>(smbuf);                 // 128 x EPAD halves (34816B)
    float* csPart = reinterpret_cast<float*>(smbuf + 36864);          // [4][TILE] partials
    const int gID = lane >> 2, tig = lane & 3;
    const int wmg = w & 3;
    float rsum[2][2] = {{0.f, 0.f}, {0.f, 0.f}};

#pragma unroll
    for (int nt = 0; nt < 8; ++nt) {
        const int lcol = wn + nt * 8 + tig * 2;
        const bool cv = (tn * TILE + lcol) < SS;
        float cs0 = 0.f, cs1 = 0.f;
#pragma unroll
        for (int mt = 0; mt < 2; ++mt)
#pragma unroll
            for (int h = 0; h < 2; ++h) {
                const int lrow = wm + mt * 16 + h * 8 + gID;
                const bool rvd = (tm * TILE + lrow) < LL;
                float e0 = cv ? exp2f(acc[mt][nt][h * 2 + 0] * EX2SC) : 0.f;
                float e1 = cv ? exp2f(acc[mt][nt][h * 2 + 1] * EX2SC) : 0.f;
                rsum[mt][h] += e0 + e1;
                if (rvd) { cs0 += e0; cs1 += e1; }
                __half2 st = __floats2half2_rn(e0, e1);
                *reinterpret_cast<__half2*>(etile + lrow * EPAD + lcol) = st;
            }
        cs0 += __shfl_xor_sync(0xffffffffu, cs0, 4);
        cs0 += __shfl_xor_sync(0xffffffffu, cs0, 8);
        cs0 += __shfl_xor_sync(0xffffffffu, cs0, 16);
        cs1 += __shfl_xor_sync(0xffffffffu, cs1, 4);
        cs1 += __shfl_xor_sync(0xffffffffu, cs1, 8);
        cs1 += __shfl_xor_sync(0xffffffffu, cs1, 16);
        if (gID == 0) {   // unique (wmg, col) per store — plain STS, no atomics
            csPart[wmg * TILE + lcol] = cs0;
            csPart[wmg * TILE + lcol + 1] = cs1;
        }
    }
#pragma unroll
    for (int mt = 0; mt < 2; ++mt)
#pragma unroll
        for (int h = 0; h < 2; ++h) {
            float r = rsum[mt][h];
            r += __shfl_xor_sync(0xffffffffu, r, 1);
            r += __shfl_xor_sync(0xffffffffu, r, 2);
            const int row = tm * TILE + wm + mt * 16 + h * 8 + gID;
            if (tig == 0 && row < LL) atomicAdd(&g_R[nb * LL + row], r);
        }
    __syncthreads();

    // coalesced e tile store: 2048 16B-chunks, 8 per thread (streaming)
#pragma unroll
    for (int q = 0; q < 8; ++q) {
        int idx = tid + q * 256;           // 0..2047
        int r = idx >> 4, c16 = idx & 15;  // row 0..127, 16B chunk 0..15
        int grow = tm * TILE + r;
        int gcol = tn * TILE + c16 * 8;    // 8 halves per chunk; SS % 8 == 0
        if (grow < LL && gcol < SS) {
            float4 v = *reinterpret_cast<const float4*>(etile + r * EPAD + c16 * 8);
            __stcs(reinterpret_cast<float4*>(g_E + ((size_t)nb * LL + grow) * SS + gcol), v);
        }
    }

    if (tid < TILE) {
        int col = tn * TILE + tid;
        if (col < SS) {
            float s = csPart[tid] + csPart[TILE + tid] +
                      csPart[2 * TILE + tid] + csPart[3 * TILE + tid];
            atomicAdd(&g_Cs[nb * SS + col], s);
        }
    }
}

// ---------------- conf = e*e*(1/R)*iC -> out (one batch, one row/block) + fused match ----------------
__global__ void __launch_bounds__(256) conf_kernel(float* __restrict__ out, long long out_size,
                                                   int nb) {
    __shared__ float sred[8];
    const int row = nb * LL + blockIdx.x;   // global row (this block exclusively owns it)
    const float ir = __frcp_rn(g_R[row]);
    const __half* ep = g_E + (size_t)row * SS;
    float* rowp = out + (size_t)row * SS;
    const float* icp = g_iC + nb * SS;
    float rmax = 0.f;
    for (int c = threadIdx.x * 4; c < SS; c += blockDim.x * 4) {
        uint2 hraw = __ldcs(reinterpret_cast<const uint2*>(ep + c));
        float4 ic = *reinterpret_cast<const float4*>(icp + c);
        float2 h01 = __half22float2(*reinterpret_cast<const __half2*>(&hraw.x));
        float2 h23 = __half22float2(*reinterpret_cast<const __half2*>(&hraw.y));
        float4 q;
        q.x = h01.x * h01.x * ir * ic.x;
        q.y = h01.y * h01.y * ir * ic.y;
        q.z = h23.x * h23.x * ir * ic.z;
        q.w = h23.y * h23.y * ir * ic.w;
        __stcs(reinterpret_cast<float4*>(rowp + c), q);
        rmax = fmaxf(fmaxf(rmax, q.x), fmaxf(q.y, fmaxf(q.z, q.w)));
    }
#pragma unroll
    for (int off = 16; off; off >>= 1)
        rmax = fmaxf(rmax, __shfl_xor_sync(0xffffffffu, rmax, off));
    if ((threadIdx.x & 31) == 0) sred[threadIdx.x >> 5] = rmax;
    __syncthreads();

    // fused match extraction (rowmax ~1e-7 << THR for this distribution; scan never runs)
    if (threadIdx.x == 0) {
        float rm = sred[0];
#pragma unroll
        for (int i = 1; i < 8; ++i) rm = fmaxf(rm, sred[i]);
        if (rm > THRV) {
            long long NLS = (long long)NB * LL * SS;
            if (out_size >= NLS + (long long)3 * NB * LL + NB) {
                for (int s = 0; s < SS; ++s) {
                    if (rowp[s] == rm) {
                        bool ismax = true;
                        for (int l2 = 0; l2 < LL; ++l2)
                            if (out[((size_t)nb * LL + l2) * SS + s] > rm) { ismax = false; break; }
                        if (ismax) {
                            out[NLS + row] = 1.0f;
                            out[NLS + (long long)NB * LL + row] = (float)s;
                            out[NLS + (long long)2 * NB * LL + row] = rm;
                            atomicAdd(&out[NLS + (long long)3 * NB * LL + nb], 1.0f);
                            break;
                        }
                    }
                }
            }
        }
    }
}

// ---------------- launch ----------------
extern "C" void kernel_launch(void* const* d_in, const int* in_sizes, int n_in,
                              void* d_out, int out_size) {
    const float* f0 = (const float*)d_in[0];
    const float* f1 = (const float*)d_in[1];
    float* out = (float*)d_out;
    long long osz = (long long)out_size;

    // one-time host objects (no device memory); same device work every call
    static cudaStream_t s_fork = nullptr;
    static cudaEvent_t s_ev0 = nullptr, s_evA = nullptr, s_evB = nullptr, s_evP1 = nullptr;
    if (s_fork == nullptr) {
        cudaStreamCreateWithFlags(&s_fork, cudaStreamNonBlocking);
        cudaEventCreateWithFlags(&s_ev0, cudaEventDisableTiming);
        cudaEventCreateWithFlags(&s_evA, cudaEventDisableTiming);
        cudaEventCreateWithFlags(&s_evB, cudaEventDisableTiming);
        cudaEventCreateWithFlags(&s_evP1, cudaEventDisableTiming);
        cudaFuncSetAttribute(gemm_kernel, cudaFuncAttributeMaxDynamicSharedMemorySize, SM_STAGES);
    }

    unsigned pgrid = (unsigned)((LPAD * CC / 4 + 255) / 256);
    dim3 grid(NT, NT);

    // fork origin: s_fork joins capture by waiting on a main-stream event first
    cudaEventRecord(s_ev0, 0);
    cudaStreamWaitEvent(s_fork, s_ev0, 0);

    // fork: prep batch 1 concurrently with main-stream prep(0)+gemm(0)
    prep_kernel<<<pgrid, 256, 0, s_fork>>>(f0, f1, out, osz, 1);
    cudaEventRecord(s_evP1, s_fork);

    prep_kernel<<<pgrid, 256>>>(f0, f1, out, osz, 0);
    gemm_kernel<<<grid, 256, SM_STAGES>>>(0);
    cudaEventRecord(s_evA, 0);                 // batch-0 sums/e complete

    cudaStreamWaitEvent(0, s_evP1, 0);
    gemm_kernel<<<grid, 256, SM_STAGES>>>(1);  // main: batch-1 GEMM

    cudaStreamWaitEvent(s_fork, s_evA, 0);     // fork: batch-0 postprocess overlaps gemm(1)
    recip_kernel<<<(SS + 255) / 256, 256, 0, s_fork>>>(0);
    conf_kernel<<<LL, 256, 0, s_fork>>>(out, osz, 0);
    cudaEventRecord(s_evB, s_fork);

    recip_kernel<<<(SS + 255) / 256, 256>>>(1);
    conf_kernel<<<LL, 256>>>(out, osz, 1);     // main stream, after gemm(1); match fused
    cudaStreamWaitEvent(0, s_evB, 0);          // join fork at the very end
}